// round 3
// baseline (speedup 1.0000x reference)
#include <cuda_runtime.h>

// Problem dims
#define BB 4
#define TT 64
#define NN 16
#define MM 8
#define DD 512
#define ROWS (BB * TT * NN * MM)   // 32768 flattened (b,t,n,m) rows

// Scratch (allocation-free rule: __device__ globals)
__device__ float g_Q[(size_t)ROWS * DD];
__device__ float g_K[(size_t)ROWS * DD];
__device__ float g_V[(size_t)ROWS * DD];
__device__ float g_W[TT * NN * MM * MM];   // softmax weights [t][n][m][k]

// ---------------------------------------------------------------------------
// Kernel 1: fused QKV projection GEMM.
// out[r, e] = sum_d x[r, d] * W[e, d] + bias[e]
// Tile: 64x64 output per block, BK=16, 256 threads, 4x4 microtile per thread.
// blockIdx.z in {0,1,2} selects (Wq,bq,Q), (Wk,bk,K), (Wv,bv,V).
// ---------------------------------------------------------------------------
__global__ __launch_bounds__(256) void qkv_gemm(
    const float* __restrict__ x,
    const float* __restrict__ Wq, const float* __restrict__ bq,
    const float* __restrict__ Wk, const float* __restrict__ bk,
    const float* __restrict__ Wv, const float* __restrict__ bv)
{
    const float* W;
    const float* bias;
    float* out;
    if (blockIdx.z == 0)      { W = Wq; bias = bq; out = g_Q; }
    else if (blockIdx.z == 1) { W = Wk; bias = bk; out = g_K; }
    else                      { W = Wv; bias = bv; out = g_V; }

    __shared__ float As[16][68];   // [k][row], padded
    __shared__ float Bs[16][68];   // [k][col], padded

    const int tid  = threadIdx.x;
    const int row0 = blockIdx.y * 64;
    const int col0 = blockIdx.x * 64;

    const int lr  = tid >> 2;          // 0..63  (row/col within tile for loads)
    const int lk4 = (tid & 3) * 4;     // 0,4,8,12 (k offset for float4 load)

    const int ty = tid >> 4;           // 0..15
    const int tx = tid & 15;           // 0..15

    float acc[4][4];
#pragma unroll
    for (int i = 0; i < 4; i++)
#pragma unroll
        for (int j = 0; j < 4; j++) acc[i][j] = 0.0f;

    for (int k0 = 0; k0 < DD; k0 += 16) {
        // Global loads (float4 along d)
        float4 av = *(const float4*)(x + (size_t)(row0 + lr) * DD + k0 + lk4);
        float4 wv = *(const float4*)(W + (size_t)(col0 + lr) * DD + k0 + lk4);

        __syncthreads();   // previous iteration done reading smem
        As[lk4 + 0][lr] = av.x;
        As[lk4 + 1][lr] = av.y;
        As[lk4 + 2][lr] = av.z;
        As[lk4 + 3][lr] = av.w;
        Bs[lk4 + 0][lr] = wv.x;
        Bs[lk4 + 1][lr] = wv.y;
        Bs[lk4 + 2][lr] = wv.z;
        Bs[lk4 + 3][lr] = wv.w;
        __syncthreads();

#pragma unroll
        for (int k = 0; k < 16; k++) {
            float4 a = *(const float4*)&As[k][ty * 4];
            float4 b = *(const float4*)&Bs[k][tx * 4];
            float ar[4] = {a.x, a.y, a.z, a.w};
            float br[4] = {b.x, b.y, b.z, b.w};
#pragma unroll
            for (int i = 0; i < 4; i++)
#pragma unroll
                for (int j = 0; j < 4; j++)
                    acc[i][j] = fmaf(ar[i], br[j], acc[i][j]);
        }
    }

    // Epilogue: add bias, vectorized store
    const int ce = col0 + tx * 4;
    float4 bv4 = *(const float4*)(bias + ce);
#pragma unroll
    for (int i = 0; i < 4; i++) {
        const int r = row0 + ty * 4 + i;
        float4 o;
        o.x = acc[i][0] + bv4.x;
        o.y = acc[i][1] + bv4.y;
        o.z = acc[i][2] + bv4.z;
        o.w = acc[i][3] + bv4.w;
        *(float4*)(out + (size_t)r * DD + ce) = o;
    }
}

// ---------------------------------------------------------------------------
// Kernel 2: attention scores + softmax.
// score[t,n,m,k] = (1/sqrt(D)) * sum_b sum_d Q[b,t,n,m,d] * K[b,t,n,k,d]
// One block per (t,n). 256 threads: b = tid/64, (m,k) = tid%64.
// ---------------------------------------------------------------------------
__global__ __launch_bounds__(256) void score_softmax()
{
    const int tn  = blockIdx.x;       // t*NN + n
    const int tid = threadIdx.x;
    const int p = tid & 63;           // m*8 + k
    const int q = tid >> 6;           // b
    const int m = p >> 3;
    const int k = p & 7;

    // row index r = ((b*T + t)*N + n)*M + m  =  b*(T*N*M) + tn*M + m
    const float4* Qb = (const float4*)(g_Q + ((size_t)q * (TT * NN * MM) + (size_t)tn * MM + m) * DD);
    const float4* Kb = (const float4*)(g_K + ((size_t)q * (TT * NN * MM) + (size_t)tn * MM + k) * DD);

    float s = 0.0f;
#pragma unroll 4
    for (int i = 0; i < DD / 4; i++) {
        float4 a = Qb[i];
        float4 b = Kb[i];
        s = fmaf(a.x, b.x, s);
        s = fmaf(a.y, b.y, s);
        s = fmaf(a.z, b.z, s);
        s = fmaf(a.w, b.w, s);
    }

    __shared__ float part[4][64];
    __shared__ float sc[64];
    __shared__ float es[64];
    part[q][p] = s;
    __syncthreads();

    if (tid < 64) {
        const float scale = 0.04419417382415922f;   // 1/sqrt(512)
        sc[tid] = (part[0][tid] + part[1][tid] + part[2][tid] + part[3][tid]) * scale;
    }
    __syncthreads();

    if (tid < 64) {
        float mx = sc[m * 8];
#pragma unroll
        for (int j = 1; j < 8; j++) mx = fmaxf(mx, sc[m * 8 + j]);
        es[tid] = expf(sc[tid] - mx);
    }
    __syncthreads();

    if (tid < 64) {
        float sum = 0.0f;
#pragma unroll
        for (int j = 0; j < 8; j++) sum += es[m * 8 + j];
        g_W[tn * 64 + tid] = es[tid] / sum;
    }
}

// ---------------------------------------------------------------------------
// Kernel 3: out[b,t,n,m,d] = sum_k w[t,n,m,k] * V[b,t,n,k,d]
// One block per (b,t,n). 256 threads: d4 = tid%128 (float4 col), mh = tid/128.
// ---------------------------------------------------------------------------
__global__ __launch_bounds__(256) void out_kernel(float* __restrict__ out)
{
    const int btn = blockIdx.x;           // (b*T + t)*N + n
    const int tid = threadIdx.x;
    const int d4  = tid & 127;
    const int mh  = tid >> 7;             // 0..1 -> m in [mh*4, mh*4+4)
    const int tn  = btn % (TT * NN);

    __shared__ float w[64];
    if (tid < 64) w[tid] = g_W[tn * 64 + tid];
    __syncthreads();

    const float4* V4 = (const float4*)(g_V + (size_t)btn * MM * DD);
    float4* O4 = (float4*)(out + (size_t)btn * MM * DD);

    float4 acc[4];
#pragma unroll
    for (int i = 0; i < 4; i++) acc[i] = make_float4(0.f, 0.f, 0.f, 0.f);

#pragma unroll
    for (int k = 0; k < 8; k++) {
        float4 v = V4[k * (DD / 4) + d4];
#pragma unroll
        for (int i = 0; i < 4; i++) {
            float wm = w[(mh * 4 + i) * 8 + k];
            acc[i].x = fmaf(wm, v.x, acc[i].x);
            acc[i].y = fmaf(wm, v.y, acc[i].y);
            acc[i].z = fmaf(wm, v.z, acc[i].z);
            acc[i].w = fmaf(wm, v.w, acc[i].w);
        }
    }

#pragma unroll
    for (int i = 0; i < 4; i++) {
        O4[(mh * 4 + i) * (DD / 4) + d4] = acc[i];
    }
}

// ---------------------------------------------------------------------------
extern "C" void kernel_launch(void* const* d_in, const int* in_sizes, int n_in,
                              void* d_out, int out_size)
{
    const float* x  = (const float*)d_in[0];
    const float* Wq = (const float*)d_in[1];
    const float* bq = (const float*)d_in[2];
    const float* Wk = (const float*)d_in[3];
    const float* bk = (const float*)d_in[4];
    const float* Wv = (const float*)d_in[5];
    const float* bv = (const float*)d_in[6];

    dim3 ggrid(DD / 64, ROWS / 64, 3);      // (8, 512, 3)
    qkv_gemm<<<ggrid, 256>>>(x, Wq, bq, Wk, bk, Wv, bv);
    score_softmax<<<TT * NN, 256>>>();
    out_kernel<<<BB * TT * NN, 256>>>((float*)d_out);
}

// round 5
// speedup vs baseline: 1.5241x; 1.5241x over previous
#include <cuda_runtime.h>
#include <cuda_bf16.h>
#include <cstdint>

// Problem dims
#define BB 4
#define TT 64
#define NN 16
#define MM 8
#define DD 512
#define ROWS (BB * TT * NN * MM)   // 32768 flattened (b,t,n,m) rows

// ---------------------------------------------------------------------------
// Scratch (__device__ globals; allocation-free rule)
// ---------------------------------------------------------------------------
__device__ float g_Q[(size_t)ROWS * DD];
__device__ float g_K[(size_t)ROWS * DD];
__device__ float g_V[(size_t)ROWS * DD];
__device__ float g_W[TT * NN * MM * MM];

__device__ __align__(16) __nv_bfloat16 g_xh[(size_t)ROWS * DD];
__device__ __align__(16) __nv_bfloat16 g_xl[(size_t)ROWS * DD];
__device__ __align__(16) __nv_bfloat16 g_wh[3 * DD * DD];
__device__ __align__(16) __nv_bfloat16 g_wl[3 * DD * DD];

// ---------------------------------------------------------------------------
// Helpers
// ---------------------------------------------------------------------------
__device__ __forceinline__ uint32_t smem_to_u32(const void* smem_ptr) {
    uint32_t addr;
    asm("{ .reg .u64 tmp; cvta.to.shared.u64 tmp, %1; cvt.u32.u64 %0, tmp; }"
        : "=r"(addr) : "l"(smem_ptr));
    return addr;
}

#define SMEM_SWIZZLE_128B(byte_offset) \
    ((byte_offset) ^ (((byte_offset) >> 3) & 0x70))

__device__ __forceinline__ void cp_async16(uint32_t dst, const void* src) {
    asm volatile("cp.async.cg.shared.global [%0], [%1], 16;"
                 :: "r"(dst), "l"(src) : "memory");
}
__device__ __forceinline__ void cp_commit() {
    asm volatile("cp.async.commit_group;" ::: "memory");
}
__device__ __forceinline__ void cp_wait1() {
    asm volatile("cp.async.wait_group 1;" ::: "memory");
}
__device__ __forceinline__ void cp_wait0() {
    asm volatile("cp.async.wait_group 0;" ::: "memory");
}

__device__ __forceinline__ void ldmatrix_x4(
    uint32_t& r0, uint32_t& r1, uint32_t& r2, uint32_t& r3, uint32_t addr)
{
    asm volatile("ldmatrix.sync.aligned.m8n8.x4.shared.b16 {%0,%1,%2,%3}, [%4];"
                 : "=r"(r0), "=r"(r1), "=r"(r2), "=r"(r3) : "r"(addr));
}

__device__ __forceinline__ void mma_16816(
    float& c0, float& c1, float& c2, float& c3,
    uint32_t a0, uint32_t a1, uint32_t a2, uint32_t a3,
    uint32_t b0, uint32_t b1)
{
    asm volatile(
        "mma.sync.aligned.m16n8k16.row.col.f32.bf16.bf16.f32 "
        "{%0,%1,%2,%3}, {%4,%5,%6,%7}, {%8,%9}, {%0,%1,%2,%3};"
        : "+f"(c0), "+f"(c1), "+f"(c2), "+f"(c3)
        : "r"(a0), "r"(a1), "r"(a2), "r"(a3), "r"(b0), "r"(b1));
}

// ---------------------------------------------------------------------------
// Convert kernels: fp32 -> bf16 hi/lo split
// ---------------------------------------------------------------------------
__device__ __forceinline__ uint32_t pack_bf16x2(__nv_bfloat16 a, __nv_bfloat16 b) {
    return (uint32_t)__bfloat16_as_ushort(a) | ((uint32_t)__bfloat16_as_ushort(b) << 16);
}

__global__ __launch_bounds__(256) void convert_x(const float* __restrict__ x)
{
    size_t i = (size_t)blockIdx.x * 256 + threadIdx.x;
    float4 v = ((const float4*)x)[i];
    __nv_bfloat16 h0 = __float2bfloat16_rn(v.x);
    __nv_bfloat16 h1 = __float2bfloat16_rn(v.y);
    __nv_bfloat16 h2 = __float2bfloat16_rn(v.z);
    __nv_bfloat16 h3 = __float2bfloat16_rn(v.w);
    __nv_bfloat16 l0 = __float2bfloat16_rn(v.x - __bfloat162float(h0));
    __nv_bfloat16 l1 = __float2bfloat16_rn(v.y - __bfloat162float(h1));
    __nv_bfloat16 l2 = __float2bfloat16_rn(v.z - __bfloat162float(h2));
    __nv_bfloat16 l3 = __float2bfloat16_rn(v.w - __bfloat162float(h3));
    ((uint2*)g_xh)[i] = make_uint2(pack_bf16x2(h0, h1), pack_bf16x2(h2, h3));
    ((uint2*)g_xl)[i] = make_uint2(pack_bf16x2(l0, l1), pack_bf16x2(l2, l3));
}

__global__ __launch_bounds__(256) void convert_w(
    const float* __restrict__ Wq, const float* __restrict__ Wk, const float* __restrict__ Wv)
{
    const float* W = (blockIdx.y == 0) ? Wq : (blockIdx.y == 1) ? Wk : Wv;
    size_t base = (size_t)blockIdx.y * (DD * DD / 4);
    size_t i = (size_t)blockIdx.x * 256 + threadIdx.x;
    float4 v = ((const float4*)W)[i];
    __nv_bfloat16 h0 = __float2bfloat16_rn(v.x);
    __nv_bfloat16 h1 = __float2bfloat16_rn(v.y);
    __nv_bfloat16 h2 = __float2bfloat16_rn(v.z);
    __nv_bfloat16 h3 = __float2bfloat16_rn(v.w);
    __nv_bfloat16 l0 = __float2bfloat16_rn(v.x - __bfloat162float(h0));
    __nv_bfloat16 l1 = __float2bfloat16_rn(v.y - __bfloat162float(h1));
    __nv_bfloat16 l2 = __float2bfloat16_rn(v.z - __bfloat162float(h2));
    __nv_bfloat16 l3 = __float2bfloat16_rn(v.w - __bfloat162float(h3));
    ((uint2*)g_wh)[base + i] = make_uint2(pack_bf16x2(h0, h1), pack_bf16x2(h2, h3));
    ((uint2*)g_wl)[base + i] = make_uint2(pack_bf16x2(l0, l1), pack_bf16x2(l2, l3));
}

// ---------------------------------------------------------------------------
// QKV projection GEMM via mma.sync bf16 (split-fp32).
// C[r,e] = sum over K'=1536: A' = [xh|xh|xl], B' = [wh|wl|wh].
// CTA: 128x128 tile, 8 warps (2 m x 4 n), warp tile 64x32.
// K streamed in 24 chunks of 64 bf16 (one SW128 row), cp.async double-buffer.
// grid = (4 n-tiles, 256 m-tiles, 3 projections), 256 threads.
// ---------------------------------------------------------------------------
#define STAGE_BYTES 32768u   // A 16KB + B 16KB
#define SMEM_DYN (2 * STAGE_BYTES + 1024)

__global__ __launch_bounds__(256, 1) void qkv_mma(
    const float* __restrict__ bq, const float* __restrict__ bk, const float* __restrict__ bv)
{
    extern __shared__ __align__(16) char dsm[];
    const uint32_t raw  = smem_to_u32(dsm);
    const uint32_t base = (raw + 1023u) & ~1023u;

    const int tid  = threadIdx.x;
    const int wid  = tid >> 5;
    const int lane = tid & 31;
    const int wm   = wid & 1;          // 0..1  (m block of 64)
    const int wn   = wid >> 1;         // 0..3  (n block of 32)
    const int gid  = lane >> 2;        // 0..7
    const int tig  = lane & 3;         // 0..3

    const int z    = blockIdx.z;       // 0:Q 1:K 2:V
    const int row0 = blockIdx.y * 128;
    const int col0 = blockIdx.x * 128;

    const __nv_bfloat16* whz = g_wh + (size_t)z * (DD * DD);
    const __nv_bfloat16* wlz = g_wl + (size_t)z * (DD * DD);

    // Load indices (8 x 16B per thread per chunk)
    const int lr = tid >> 3;           // 0..31 ... wait: 256 threads -> idx = tid + j*256
    (void)lr;

    // Precomputed swizzled ldmatrix base addresses (kk=0); kk advances via ^ (kk<<5)
    // A: row = wm*64 + mf*16 + (lane&15), kbyte = (lane>>4)*16
    uint32_t aAddr[4];
#pragma unroll
    for (int mf = 0; mf < 4; mf++) {
        int r = wm * 64 + mf * 16 + (lane & 15);
        uint32_t t = (uint32_t)((lane >> 4) * 16);
        aAddr[mf] = base + r * 128 + (t ^ ((uint32_t)(r & 7) * 16));
    }
    // B: n = wn*32 + bh*16 + (lane&7) + ((lane>>4)&1)*8, kbyte = ((lane>>3)&1)*16
    uint32_t bAddr[2];
#pragma unroll
    for (int bh = 0; bh < 2; bh++) {
        int n = wn * 32 + bh * 16 + (lane & 7) + ((lane >> 4) & 1) * 8;
        uint32_t t = (uint32_t)(((lane >> 3) & 1) * 16);
        bAddr[bh] = base + 16384u + n * 128 + (t ^ ((uint32_t)(n & 7) * 16));
    }

    float c[4][4][4];
#pragma unroll
    for (int mf = 0; mf < 4; mf++)
#pragma unroll
        for (int nf = 0; nf < 4; nf++)
#pragma unroll
            for (int q = 0; q < 4; q++) c[mf][nf][q] = 0.0f;

    // ---- cp.async loader for chunk c into stage s ----
    auto issue_chunk = [&](int c, int s) {
        const __nv_bfloat16* Asrc = (c < 16) ? g_xh : g_xl;
        const __nv_bfloat16* Bsrc = (c >= 8 && c < 16) ? wlz : whz;
        const int koff = (c & 7) * 64;
        const uint32_t stage = base + (uint32_t)s * STAGE_BYTES;
#pragma unroll
        for (int j = 0; j < 4; j++) {
            int idx = tid + j * 256;
            int r = idx >> 3, o = idx & 7;
            uint32_t bo = (uint32_t)(r * 128 + o * 16);
            cp_async16(stage + SMEM_SWIZZLE_128B(bo),
                       Asrc + (size_t)(row0 + r) * DD + koff + o * 8);
        }
#pragma unroll
        for (int j = 0; j < 4; j++) {
            int idx = tid + j * 256;
            int n = idx >> 3, o = idx & 7;
            uint32_t bo = (uint32_t)(n * 128 + o * 16);
            cp_async16(stage + 16384u + SMEM_SWIZZLE_128B(bo),
                       Bsrc + (size_t)(col0 + n) * DD + koff + o * 8);
        }
        cp_commit();
    };

    issue_chunk(0, 0);

    for (int ck = 0; ck < 24; ck++) {
        const int s = ck & 1;
        if (ck + 1 < 24) issue_chunk(ck + 1, (ck + 1) & 1);
        if (ck + 1 < 24) cp_wait1(); else cp_wait0();
        __syncthreads();

        const uint32_t soff = (uint32_t)s * STAGE_BYTES;
#pragma unroll
        for (int kk = 0; kk < 4; kk++) {
            const uint32_t kx = (uint32_t)(kk << 5);
            uint32_t a[4][4];
#pragma unroll
            for (int mf = 0; mf < 4; mf++)
                ldmatrix_x4(a[mf][0], a[mf][1], a[mf][2], a[mf][3],
                            (aAddr[mf] + soff) ^ kx);
            uint32_t b[4][2];
#pragma unroll
            for (int bh = 0; bh < 2; bh++) {
                uint32_t r0, r1, r2, r3;
                ldmatrix_x4(r0, r1, r2, r3, (bAddr[bh] + soff) ^ kx);
                b[bh * 2 + 0][0] = r0; b[bh * 2 + 0][1] = r1;
                b[bh * 2 + 1][0] = r2; b[bh * 2 + 1][1] = r3;
            }
#pragma unroll
            for (int mf = 0; mf < 4; mf++)
#pragma unroll
                for (int nf = 0; nf < 4; nf++)
                    mma_16816(c[mf][nf][0], c[mf][nf][1], c[mf][nf][2], c[mf][nf][3],
                              a[mf][0], a[mf][1], a[mf][2], a[mf][3],
                              b[nf][0], b[nf][1]);
        }
        __syncthreads();
    }

    // Epilogue: bias + store fp32
    float* out = (z == 0) ? g_Q : (z == 1) ? g_K : g_V;
    const float* bias = (z == 0) ? bq : (z == 1) ? bk : bv;

#pragma unroll
    for (int nf = 0; nf < 4; nf++) {
        const int col = col0 + wn * 32 + nf * 8 + tig * 2;
        float2 bb = *(const float2*)(bias + col);
#pragma unroll
        for (int mf = 0; mf < 4; mf++) {
            const int r0 = row0 + wm * 64 + mf * 16 + gid;
            float2 v0 = make_float2(c[mf][nf][0] + bb.x, c[mf][nf][1] + bb.y);
            float2 v1 = make_float2(c[mf][nf][2] + bb.x, c[mf][nf][3] + bb.y);
            *(float2*)(out + (size_t)r0 * DD + col)       = v0;
            *(float2*)(out + (size_t)(r0 + 8) * DD + col) = v1;
        }
    }
}

// ---------------------------------------------------------------------------
// Kernel 2: attention scores + softmax
// ---------------------------------------------------------------------------
__global__ __launch_bounds__(256) void score_softmax()
{
    const int tn  = blockIdx.x;
    const int tid = threadIdx.x;
    const int p = tid & 63;
    const int q = tid >> 6;
    const int m = p >> 3;
    const int k = p & 7;

    const float4* Qb = (const float4*)(g_Q + ((size_t)q * (TT * NN * MM) + (size_t)tn * MM + m) * DD);
    const float4* Kb = (const float4*)(g_K + ((size_t)q * (TT * NN * MM) + (size_t)tn * MM + k) * DD);

    float s = 0.0f;
#pragma unroll 4
    for (int i = 0; i < DD / 4; i++) {
        float4 a = Qb[i];
        float4 b = Kb[i];
        s = fmaf(a.x, b.x, s);
        s = fmaf(a.y, b.y, s);
        s = fmaf(a.z, b.z, s);
        s = fmaf(a.w, b.w, s);
    }

    __shared__ float part[4][64];
    __shared__ float sc[64];
    __shared__ float es[64];
    part[q][p] = s;
    __syncthreads();

    if (tid < 64) {
        const float scale = 0.04419417382415922f;
        sc[tid] = (part[0][tid] + part[1][tid] + part[2][tid] + part[3][tid]) * scale;
    }
    __syncthreads();

    if (tid < 64) {
        float mx = sc[m * 8];
#pragma unroll
        for (int j = 1; j < 8; j++) mx = fmaxf(mx, sc[m * 8 + j]);
        es[tid] = expf(sc[tid] - mx);
    }
    __syncthreads();

    if (tid < 64) {
        float sum = 0.0f;
#pragma unroll
        for (int j = 0; j < 8; j++) sum += es[m * 8 + j];
        g_W[tn * 64 + tid] = es[tid] / sum;
    }
}

// ---------------------------------------------------------------------------
// Kernel 3: weighted V sum
// ---------------------------------------------------------------------------
__global__ __launch_bounds__(256) void out_kernel(float* __restrict__ out)
{
    const int btn = blockIdx.x;
    const int tid = threadIdx.x;
    const int d4  = tid & 127;
    const int mh  = tid >> 7;
    const int tn  = btn % (TT * NN);

    __shared__ float w[64];
    if (tid < 64) w[tid] = g_W[tn * 64 + tid];
    __syncthreads();

    const float4* V4 = (const float4*)(g_V + (size_t)btn * MM * DD);
    float4* O4 = (float4*)(out + (size_t)btn * MM * DD);

    float4 acc[4];
#pragma unroll
    for (int i = 0; i < 4; i++) acc[i] = make_float4(0.f, 0.f, 0.f, 0.f);

#pragma unroll
    for (int k = 0; k < 8; k++) {
        float4 v = V4[k * (DD / 4) + d4];
#pragma unroll
        for (int i = 0; i < 4; i++) {
            float wm = w[(mh * 4 + i) * 8 + k];
            acc[i].x = fmaf(wm, v.x, acc[i].x);
            acc[i].y = fmaf(wm, v.y, acc[i].y);
            acc[i].z = fmaf(wm, v.z, acc[i].z);
            acc[i].w = fmaf(wm, v.w, acc[i].w);
        }
    }

#pragma unroll
    for (int i = 0; i < 4; i++) {
        O4[(mh * 4 + i) * (DD / 4) + d4] = acc[i];
    }
}

// ---------------------------------------------------------------------------
extern "C" void kernel_launch(void* const* d_in, const int* in_sizes, int n_in,
                              void* d_out, int out_size)
{
    const float* x  = (const float*)d_in[0];
    const float* Wq = (const float*)d_in[1];
    const float* bq = (const float*)d_in[2];
    const float* Wk = (const float*)d_in[3];
    const float* bk = (const float*)d_in[4];
    const float* Wv = (const float*)d_in[5];
    const float* bv = (const float*)d_in[6];

    cudaFuncSetAttribute(qkv_mma, cudaFuncAttributeMaxDynamicSharedMemorySize, SMEM_DYN);

    convert_x<<<(ROWS * DD / 4) / 256, 256>>>(x);
    convert_w<<<dim3((DD * DD / 4) / 256, 3), 256>>>(Wq, Wk, Wv);
    qkv_mma<<<dim3(4, ROWS / 128, 3), 256, SMEM_DYN>>>(bq, bk, bv);
    score_softmax<<<TT * NN, 256>>>();
    out_kernel<<<BB * TT * NN, 256>>>((float*)d_out);
}

// round 7
// speedup vs baseline: 3.4388x; 2.2562x over previous
#include <cuda_runtime.h>
#include <cuda_bf16.h>
#include <cstdint>

// Problem dims
#define BB 4
#define TT 64
#define NN 16
#define MM 8
#define DD 512
#define ROWS (BB * TT * NN * MM)   // 32768 flattened (b,t,n,m) rows
#define TNM  (TT * NN * MM)

// ---------------------------------------------------------------------------
// Scratch (__device__ globals; allocation-free rule)
// ---------------------------------------------------------------------------
__device__ float g_Q[(size_t)ROWS * DD];
__device__ float g_K[(size_t)ROWS * DD];
__device__ float g_V[(size_t)ROWS * DD];
__device__ float g_W[TT * NN * MM * MM];

__device__ __align__(16) __nv_bfloat16 g_xh[(size_t)ROWS * DD];
__device__ __align__(16) __nv_bfloat16 g_xl[(size_t)ROWS * DD];
__device__ __align__(16) __nv_bfloat16 g_wh[3 * DD * DD];
__device__ __align__(16) __nv_bfloat16 g_wl[3 * DD * DD];

// ---------------------------------------------------------------------------
// Helpers
// ---------------------------------------------------------------------------
__device__ __forceinline__ uint32_t smem_to_u32(const void* smem_ptr) {
    uint32_t addr;
    asm("{ .reg .u64 tmp; cvta.to.shared.u64 tmp, %1; cvt.u32.u64 %0, tmp; }"
        : "=r"(addr) : "l"(smem_ptr));
    return addr;
}

#define SMEM_SWIZZLE_128B(byte_offset) \
    ((byte_offset) ^ (((byte_offset) >> 3) & 0x70))

__device__ __forceinline__ void cp_async16(uint32_t dst, const void* src) {
    asm volatile("cp.async.cg.shared.global [%0], [%1], 16;"
                 :: "r"(dst), "l"(src) : "memory");
}
__device__ __forceinline__ void cp_commit() {
    asm volatile("cp.async.commit_group;" ::: "memory");
}
__device__ __forceinline__ void cp_wait2() {
    asm volatile("cp.async.wait_group 2;" ::: "memory");
}
__device__ __forceinline__ void cp_wait1() {
    asm volatile("cp.async.wait_group 1;" ::: "memory");
}
__device__ __forceinline__ void cp_wait0() {
    asm volatile("cp.async.wait_group 0;" ::: "memory");
}

__device__ __forceinline__ void ldmatrix_x4(
    uint32_t& r0, uint32_t& r1, uint32_t& r2, uint32_t& r3, uint32_t addr)
{
    asm volatile("ldmatrix.sync.aligned.m8n8.x4.shared.b16 {%0,%1,%2,%3}, [%4];"
                 : "=r"(r0), "=r"(r1), "=r"(r2), "=r"(r3) : "r"(addr));
}

__device__ __forceinline__ void mma_16816(
    float& c0, float& c1, float& c2, float& c3,
    uint32_t a0, uint32_t a1, uint32_t a2, uint32_t a3,
    uint32_t b0, uint32_t b1)
{
    asm volatile(
        "mma.sync.aligned.m16n8k16.row.col.f32.bf16.bf16.f32 "
        "{%0,%1,%2,%3}, {%4,%5,%6,%7}, {%8,%9}, {%0,%1,%2,%3};"
        : "+f"(c0), "+f"(c1), "+f"(c2), "+f"(c3)
        : "r"(a0), "r"(a1), "r"(a2), "r"(a3), "r"(b0), "r"(b1));
}

// ---------------------------------------------------------------------------
// Convert kernels: fp32 -> bf16 hi/lo split
// ---------------------------------------------------------------------------
__device__ __forceinline__ uint32_t pack_bf16x2(__nv_bfloat16 a, __nv_bfloat16 b) {
    return (uint32_t)__bfloat16_as_ushort(a) | ((uint32_t)__bfloat16_as_ushort(b) << 16);
}

__global__ __launch_bounds__(256) void convert_x(const float* __restrict__ x)
{
    size_t i = (size_t)blockIdx.x * 256 + threadIdx.x;
    float4 v = ((const float4*)x)[i];
    __nv_bfloat16 h0 = __float2bfloat16_rn(v.x);
    __nv_bfloat16 h1 = __float2bfloat16_rn(v.y);
    __nv_bfloat16 h2 = __float2bfloat16_rn(v.z);
    __nv_bfloat16 h3 = __float2bfloat16_rn(v.w);
    __nv_bfloat16 l0 = __float2bfloat16_rn(v.x - __bfloat162float(h0));
    __nv_bfloat16 l1 = __float2bfloat16_rn(v.y - __bfloat162float(h1));
    __nv_bfloat16 l2 = __float2bfloat16_rn(v.z - __bfloat162float(h2));
    __nv_bfloat16 l3 = __float2bfloat16_rn(v.w - __bfloat162float(h3));
    ((uint2*)g_xh)[i] = make_uint2(pack_bf16x2(h0, h1), pack_bf16x2(h2, h3));
    ((uint2*)g_xl)[i] = make_uint2(pack_bf16x2(l0, l1), pack_bf16x2(l2, l3));
}

__global__ __launch_bounds__(256) void convert_w(
    const float* __restrict__ Wq, const float* __restrict__ Wk, const float* __restrict__ Wv)
{
    const float* W = (blockIdx.y == 0) ? Wq : (blockIdx.y == 1) ? Wk : Wv;
    size_t base = (size_t)blockIdx.y * (DD * DD / 4);
    size_t i = (size_t)blockIdx.x * 256 + threadIdx.x;
    float4 v = ((const float4*)W)[i];
    __nv_bfloat16 h0 = __float2bfloat16_rn(v.x);
    __nv_bfloat16 h1 = __float2bfloat16_rn(v.y);
    __nv_bfloat16 h2 = __float2bfloat16_rn(v.z);
    __nv_bfloat16 h3 = __float2bfloat16_rn(v.w);
    __nv_bfloat16 l0 = __float2bfloat16_rn(v.x - __bfloat162float(h0));
    __nv_bfloat16 l1 = __float2bfloat16_rn(v.y - __bfloat162float(h1));
    __nv_bfloat16 l2 = __float2bfloat16_rn(v.z - __bfloat162float(h2));
    __nv_bfloat16 l3 = __float2bfloat16_rn(v.w - __bfloat162float(h3));
    ((uint2*)g_wh)[base + i] = make_uint2(pack_bf16x2(h0, h1), pack_bf16x2(h2, h3));
    ((uint2*)g_wl)[base + i] = make_uint2(pack_bf16x2(l0, l1), pack_bf16x2(l2, l3));
}

// ---------------------------------------------------------------------------
// QKV projection GEMM via mma.sync bf16 (split-fp32).
// CTA: 128x128 tile, 4 warps (2m x 2n), warp tile 64x64.
// K'=1536 streamed in 24 chunks of 64 bf16, 3-stage cp.async pipeline.
// grid = (4 n-tiles, 256 m-tiles, 3 projections), 128 threads.
// ---------------------------------------------------------------------------
#define STAGE_BYTES 32768u   // A 16KB + B 16KB
#define SMEM_DYN (3 * STAGE_BYTES + 1024)

__global__ __launch_bounds__(128, 1) void qkv_mma(
    const float* __restrict__ bq, const float* __restrict__ bk, const float* __restrict__ bv)
{
    extern __shared__ __align__(16) char dsm[];
    const uint32_t raw  = smem_to_u32(dsm);
    const uint32_t base = (raw + 1023u) & ~1023u;

    const int tid  = threadIdx.x;
    const int wid  = tid >> 5;
    const int lane = tid & 31;
    const int wm   = wid & 1;          // m block of 64
    const int wn   = wid >> 1;         // n block of 64
    const int gid  = lane >> 2;
    const int tig  = lane & 3;

    const int z    = blockIdx.z;
    const int row0 = blockIdx.y * 128;
    const int col0 = blockIdx.x * 128;

    const __nv_bfloat16* whz = g_wh + (size_t)z * (DD * DD);
    const __nv_bfloat16* wlz = g_wl + (size_t)z * (DD * DD);

    // Swizzled ldmatrix base addresses (kk=0); kk advances via ^(kk<<5)
    uint32_t aAddr[4];
#pragma unroll
    for (int mf = 0; mf < 4; mf++) {
        int r = wm * 64 + mf * 16 + (lane & 15);
        uint32_t t = (uint32_t)((lane >> 4) * 16);
        aAddr[mf] = base + r * 128 + (t ^ ((uint32_t)(r & 7) * 16));
    }
    uint32_t bAddr[4];
#pragma unroll
    for (int bh = 0; bh < 4; bh++) {
        int n = wn * 64 + bh * 16 + (lane & 7) + ((lane >> 4) & 1) * 8;
        uint32_t t = (uint32_t)(((lane >> 3) & 1) * 16);
        bAddr[bh] = base + 16384u + n * 128 + (t ^ ((uint32_t)(n & 7) * 16));
    }

    float c[4][8][4];
#pragma unroll
    for (int mf = 0; mf < 4; mf++)
#pragma unroll
        for (int nf = 0; nf < 8; nf++)
#pragma unroll
            for (int q = 0; q < 4; q++) c[mf][nf][q] = 0.0f;

    auto issue_chunk = [&](int ci, int s) {
        const __nv_bfloat16* Asrc = (ci < 16) ? g_xh : g_xl;
        const __nv_bfloat16* Bsrc = (ci >= 8 && ci < 16) ? wlz : whz;
        const int koff = (ci & 7) * 64;
        const uint32_t stage = base + (uint32_t)s * STAGE_BYTES;
#pragma unroll
        for (int j = 0; j < 8; j++) {
            int idx = tid + j * 128;
            int r = idx >> 3, o = idx & 7;
            uint32_t bo = (uint32_t)(r * 128 + o * 16);
            cp_async16(stage + SMEM_SWIZZLE_128B(bo),
                       Asrc + (size_t)(row0 + r) * DD + koff + o * 8);
        }
#pragma unroll
        for (int j = 0; j < 8; j++) {
            int idx = tid + j * 128;
            int n = idx >> 3, o = idx & 7;
            uint32_t bo = (uint32_t)(n * 128 + o * 16);
            cp_async16(stage + 16384u + SMEM_SWIZZLE_128B(bo),
                       Bsrc + (size_t)(col0 + n) * DD + koff + o * 8);
        }
        cp_commit();
    };

    issue_chunk(0, 0);
    issue_chunk(1, 1);

    for (int ck = 0; ck < 24; ck++) {
        if (ck + 2 < 24) issue_chunk(ck + 2, (ck + 2) % 3);
        if (ck < 22) cp_wait2();
        else if (ck == 22) cp_wait1();
        else cp_wait0();
        __syncthreads();

        const uint32_t soff = (uint32_t)(ck % 3) * STAGE_BYTES;
#pragma unroll
        for (int kk = 0; kk < 4; kk++) {
            const uint32_t kx = (uint32_t)(kk << 5);
            uint32_t a[4][4];
#pragma unroll
            for (int mf = 0; mf < 4; mf++)
                ldmatrix_x4(a[mf][0], a[mf][1], a[mf][2], a[mf][3],
                            (aAddr[mf] + soff) ^ kx);
            uint32_t b[8][2];
#pragma unroll
            for (int bh = 0; bh < 4; bh++) {
                uint32_t r0, r1, r2, r3;
                ldmatrix_x4(r0, r1, r2, r3, (bAddr[bh] + soff) ^ kx);
                b[bh * 2 + 0][0] = r0; b[bh * 2 + 0][1] = r1;
                b[bh * 2 + 1][0] = r2; b[bh * 2 + 1][1] = r3;
            }
#pragma unroll
            for (int mf = 0; mf < 4; mf++)
#pragma unroll
                for (int nf = 0; nf < 8; nf++)
                    mma_16816(c[mf][nf][0], c[mf][nf][1], c[mf][nf][2], c[mf][nf][3],
                              a[mf][0], a[mf][1], a[mf][2], a[mf][3],
                              b[nf][0], b[nf][1]);
        }
        __syncthreads();
    }

    float* out = (z == 0) ? g_Q : (z == 1) ? g_K : g_V;
    const float* bias = (z == 0) ? bq : (z == 1) ? bk : bv;

#pragma unroll
    for (int nf = 0; nf < 8; nf++) {
        const int col = col0 + wn * 64 + nf * 8 + tig * 2;
        float2 bb = *(const float2*)(bias + col);
#pragma unroll
        for (int mf = 0; mf < 4; mf++) {
            const int r0 = row0 + wm * 64 + mf * 16 + gid;
            float2 v0 = make_float2(c[mf][nf][0] + bb.x, c[mf][nf][1] + bb.y);
            float2 v1 = make_float2(c[mf][nf][2] + bb.x, c[mf][nf][3] + bb.y);
            *(float2*)(out + (size_t)r0 * DD + col)       = v0;
            *(float2*)(out + (size_t)(r0 + 8) * DD + col) = v1;
        }
    }
}

// ---------------------------------------------------------------------------
// Kernel 2: attention scores + softmax (smem-staged, register-tiled 4x4).
// One block per (t,n). 256 threads = 4 b x 4 tiles(4m x 4k) x 16 d-slices.
// d processed in 4 chunks of 128; each thread accumulates a 4x4 partial
// over its 8-d slice, partials reduced via padded smem, then softmax.
// ---------------------------------------------------------------------------
__global__ __launch_bounds__(256) void score_softmax()
{
    __shared__ float sQ[4096];        // [4b][8m][128d]
    __shared__ float sK[4096];
    __shared__ float part[64 * 65];   // [h=b*16+slice][pair], padded
    __shared__ float sc[64];
    __shared__ float es[64];

    const int tn  = blockIdx.x;
    const int tid = threadIdx.x;
    const int b    = tid >> 6;
    const int r    = tid & 63;
    const int tile = r >> 4;          // 0..3
    const int slc  = r & 15;          // d-slice
    const int mt   = tile >> 1;       // m block of 4
    const int kt   = tile & 1;        // k block of 4

    float acc[4][4];
#pragma unroll
    for (int i = 0; i < 4; i++)
#pragma unroll
        for (int j = 0; j < 4; j++) acc[i][j] = 0.0f;

    const float4* Q4 = (const float4*)g_Q;
    const float4* K4 = (const float4*)g_K;

    for (int ch = 0; ch < 4; ch++) {
        // Load 4b x 8rows x 128d for Q and K (1024 float4 each)
        __syncthreads();
#pragma unroll
        for (int j = 0; j < 4; j++) {
            int idx = tid + j * 256;
            int lb = idx >> 8, lr = (idx >> 5) & 7, o = idx & 31;
            size_t grow = (size_t)lb * TNM + (size_t)tn * MM + lr;
            ((float4*)sQ)[(lb * 8 + lr) * 32 + o] = Q4[grow * (DD / 4) + ch * 32 + o];
            ((float4*)sK)[(lb * 8 + lr) * 32 + o] = K4[grow * (DD / 4) + ch * 32 + o];
        }
        __syncthreads();

        // Each thread: 4x4 outputs over d = {slc*4, 64+slc*4} (2 float4)
#pragma unroll
        for (int j = 0; j < 2; j++) {
            const int d4 = j * 16 + slc;
            float4 qf[4], kf[4];
#pragma unroll
            for (int i = 0; i < 4; i++)
                qf[i] = ((const float4*)sQ)[(b * 8 + mt * 4 + i) * 32 + d4];
#pragma unroll
            for (int i = 0; i < 4; i++)
                kf[i] = ((const float4*)sK)[(b * 8 + kt * 4 + i) * 32 + d4];
#pragma unroll
            for (int i = 0; i < 4; i++)
#pragma unroll
                for (int kx = 0; kx < 4; kx++) {
                    acc[i][kx] = fmaf(qf[i].x, kf[kx].x, acc[i][kx]);
                    acc[i][kx] = fmaf(qf[i].y, kf[kx].y, acc[i][kx]);
                    acc[i][kx] = fmaf(qf[i].z, kf[kx].z, acc[i][kx]);
                    acc[i][kx] = fmaf(qf[i].w, kf[kx].w, acc[i][kx]);
                }
        }
    }

    // Write partials: h = b*16+slc, pair = m*8+k
    const int h = b * 16 + slc;
#pragma unroll
    for (int i = 0; i < 4; i++)
#pragma unroll
        for (int kx = 0; kx < 4; kx++) {
            int pair = (mt * 4 + i) * 8 + (kt * 4 + kx);
            part[h * 65 + pair] = acc[i][kx];
        }
    __syncthreads();

    if (tid < 64) {
        float s = 0.0f;
#pragma unroll
        for (int i = 0; i < 64; i++) s += part[i * 65 + tid];
        sc[tid] = s * 0.04419417382415922f;   // 1/sqrt(512)
    }
    __syncthreads();

    if (tid < 64) {
        const int m = tid >> 3;
        float mx = sc[m * 8];
#pragma unroll
        for (int j = 1; j < 8; j++) mx = fmaxf(mx, sc[m * 8 + j]);
        es[tid] = expf(sc[tid] - mx);
    }
    __syncthreads();

    if (tid < 64) {
        const int m = tid >> 3;
        float sum = 0.0f;
#pragma unroll
        for (int j = 0; j < 8; j++) sum += es[m * 8 + j];
        g_W[tn * 64 + tid] = es[tid] / sum;
    }
}

// ---------------------------------------------------------------------------
// Kernel 3: weighted V sum
// ---------------------------------------------------------------------------
__global__ __launch_bounds__(256) void out_kernel(float* __restrict__ out)
{
    const int btn = blockIdx.x;
    const int tid = threadIdx.x;
    const int d4  = tid & 127;
    const int mh  = tid >> 7;
    const int tn  = btn % (TT * NN);

    __shared__ float w[64];
    if (tid < 64) w[tid] = g_W[tn * 64 + tid];
    __syncthreads();

    const float4* V4 = (const float4*)(g_V + (size_t)btn * MM * DD);
    float4* O4 = (float4*)(out + (size_t)btn * MM * DD);

    float4 acc[4];
#pragma unroll
    for (int i = 0; i < 4; i++) acc[i] = make_float4(0.f, 0.f, 0.f, 0.f);

#pragma unroll
    for (int k = 0; k < 8; k++) {
        float4 v = V4[k * (DD / 4) + d4];
#pragma unroll
        for (int i = 0; i < 4; i++) {
            float wm = w[(mh * 4 + i) * 8 + k];
            acc[i].x = fmaf(wm, v.x, acc[i].x);
            acc[i].y = fmaf(wm, v.y, acc[i].y);
            acc[i].z = fmaf(wm, v.z, acc[i].z);
            acc[i].w = fmaf(wm, v.w, acc[i].w);
        }
    }

#pragma unroll
    for (int i = 0; i < 4; i++) {
        O4[(mh * 4 + i) * (DD / 4) + d4] = acc[i];
    }
}

// ---------------------------------------------------------------------------
extern "C" void kernel_launch(void* const* d_in, const int* in_sizes, int n_in,
                              void* d_out, int out_size)
{
    const float* x  = (const float*)d_in[0];
    const float* Wq = (const float*)d_in[1];
    const float* bq = (const float*)d_in[2];
    const float* Wk = (const float*)d_in[3];
    const float* bk = (const float*)d_in[4];
    const float* Wv = (const float*)d_in[5];
    const float* bv = (const float*)d_in[6];

    cudaFuncSetAttribute(qkv_mma, cudaFuncAttributeMaxDynamicSharedMemorySize, SMEM_DYN);

    convert_x<<<(ROWS * DD / 4) / 256, 256>>>(x);
    convert_w<<<dim3((DD * DD / 4) / 256, 3), 256>>>(Wq, Wk, Wv);
    qkv_mma<<<dim3(4, ROWS / 128, 3), 128, SMEM_DYN>>>(bq, bk, bv);
    score_softmax<<<TT * NN, 256>>>();
    out_kernel<<<BB * TT * NN, 256>>>((float*)d_out);
}